// round 9
// baseline (speedup 1.0000x reference)
#include <cuda_runtime.h>

#define BATCH   4096
#define D       128
#define NP      16
#define HID     256
#define XSTRIDE 144           // D + NPARAMS

typedef unsigned long long u64;

// ---------------- packed f32x2 helpers (sm_100a) ----------------
__device__ __forceinline__ u64 pk(float lo, float hi) {
    u64 r; asm("mov.b64 %0, {%1, %2};" : "=l"(r) : "f"(lo), "f"(hi)); return r;
}
__device__ __forceinline__ void upk(float& lo, float& hi, u64 v) {
    asm("mov.b64 {%0, %1}, %2;" : "=f"(lo), "=f"(hi) : "l"(v));
}
__device__ __forceinline__ u64 fma2(u64 a, u64 b, u64 c) {
    u64 r; asm("fma.rn.f32x2 %0, %1, %2, %3;" : "=l"(r) : "l"(a), "l"(b), "l"(c)); return r;
}
__device__ __forceinline__ u64 mul2(u64 a, u64 b) {
    u64 r; asm("mul.rn.f32x2 %0, %1, %2;" : "=l"(r) : "l"(a), "l"(b)); return r;
}
__device__ __forceinline__ u64 add2(u64 a, u64 b) {
    u64 r; asm("add.rn.f32x2 %0, %1, %2;" : "=l"(r) : "l"(a), "l"(b)); return r;
}

// ---------------- cp.async helpers ----------------
__device__ __forceinline__ unsigned smem_u32(const void* p) {
    return (unsigned)__cvta_generic_to_shared(p);
}
__device__ __forceinline__ void cp16(float* dst, const float* src) {
    asm volatile("cp.async.cg.shared.global [%0], [%1], 16;\n"
                 :: "r"(smem_u32(dst)), "l"(src));
}
__device__ __forceinline__ void cp_commit() {
    asm volatile("cp.async.commit_group;\n");
}
template<int N> __device__ __forceinline__ void cp_wait() {
    asm volatile("cp.async.wait_group %0;\n" :: "n"(N));
}

// ============================================================================
// FUSED kernel, 2-blocks/SM edition.
// BM=16 rows/block (+1 predecessor row for the flat-roll wrap coupling),
// TPB=256, weight chunks 32-wide double-buffered -> smem 109.6 KB/block
// -> 2 co-resident blocks/SM (grid 256 = single wave on 148 SMs).
// __launch_bounds__(256,2) caps regs at 128 so the regfile fits both blocks.
//
// MLP: thread owns neurons (j, j+128), row group g=tid>>7 (8 rows; g==1 also
// owns logical row 16 = global row row0-1). f32x2 packed along K, both fma2
// operands pre-packed (weights LDS.128 stride-36 conflict-free; activations
// broadcast LDS.128). One __syncthreads per chunk: wait<0>; SYNC; stage(next);
// compute(cur).
//
// Final layer -> smem overlays in hB: w2s[16][128], cs[16][128] with cs[-1]
// = coupling of flat index row0*128-1 (branchless flat-roll read).
//
// ODE: warp wid integrates rows 2wid, 2wid+1 (4 elems/lane), RKN4, NSTEPS=8.
// Error model (measured): rel_err(N) = 1.4402/1.4402/1.4402/1.4394e-4 for
// N=256/192/64/12 -> truncation at N=12 <= ~1e-5 -> e(8) ~ 5e-5, RSS safe.
// ============================================================================
#define TPB    256
#define BM     16
#define NSTEPS 8

// smem floats: hA 17*256=4352 | hB 4352 | WcA 256*36 | WcB 256*36 | P 17*16
#define SM_HB  4352
#define SM_WA  8704
#define SM_WB  17920
#define SM_P   27136
#define SMEM_FLOATS (SM_P + 17 * 16)            // 27408
#define SMEM_BYTES  (SMEM_FLOATS * 4)           // 109632 B

// stage one 256x32 weight chunk (kc = starting k) into Wdst (row stride 36)
__device__ __forceinline__ void stage_chunk(float* Wdst, const float* __restrict__ Wg,
                                            int kc, int tid) {
    #pragma unroll
    for (int i = 0; i < 8; i++) {
        int c  = tid + i * TPB;        // 0..2047 16B-chunks
        int jj = c >> 3;               // weight row 0..255
        int kk = (c & 7) * 4;          // 0..28
        cp16(Wdst + jj * 36 + kk, Wg + jj * HID + kc + kk);
    }
}

__global__ void __launch_bounds__(TPB, 2) fused_kernel(
    const float* __restrict__ x,
    const float* __restrict__ w_in, const float* __restrict__ b_in,
    const float* __restrict__ w0,   const float* __restrict__ b0,
    const float* __restrict__ w1,   const float* __restrict__ b1,
    const float* __restrict__ w_out,const float* __restrict__ b_out,
    float* __restrict__ out)
{
    extern __shared__ float sm[];
    float* hA  = sm;                  // [17 rows][256 neurons]
    float* hB  = sm + SM_HB;
    float* WcA = sm + SM_WA;
    float* WcB = sm + SM_WB;
    float* P   = sm + SM_P;           // [17][16]
    // post-layer-2 overlays in hB (hB dead during layer 2: it reads hA)
    float* w2s = hB;                  // [16][128]
    float* cs  = hB + 2052;           // [16][128], 16B-aligned; cs[-1] = csx

    const int tid  = threadIdx.x;
    const int j    = tid & 127;        // neuron pair (j, j+128)
    const int g    = tid >> 7;         // row group: rows 8g..8g+7 (+row 16 if g==1)
    const int wid  = tid >> 5;
    const int lane = tid & 31;
    const int row0 = blockIdx.x * BM;

    // Stage params P[r][k] for 17 logical rows (row 16 = global row row0-1)
    for (int idx = tid; idx < 17 * NP; idx += TPB) {
        int r = idx >> 4, k = idx & 15;
        int grow = (r < BM) ? (row0 + r) : ((row0 + BATCH - 1) & (BATCH - 1));
        P[idx] = x[grow * XSTRIDE + D + k];
    }
    // Stage w_in with row stride 17 into WcA
    for (int idx = tid; idx < HID * NP; idx += TPB) {
        int jj = idx >> 4, k = idx & 15;
        WcA[jj * 17 + k] = w_in[idx];
    }
    // Prefetch layer-0 chunk 0 into WcB (overlaps with the input layer)
    stage_chunk(WcB, w0, 0, tid);
    cp_commit();
    __syncthreads();

    // ---- input layer: 16 -> 256, relu ----
    {
        float wa[16], wb[16];
        #pragma unroll
        for (int k = 0; k < 16; k++) {
            wa[k] = WcA[j * 17 + k];
            wb[k] = WcA[(j + 128) * 17 + k];
        }
        float ba = b_in[j], bb = b_in[j + 128];
        #pragma unroll
        for (int r = 0; r < 9; r++) {
            if (r == 8 && g != 1) break;           // uniform per warp
            int L = (r < 8) ? (8 * g + r) : 16;
            float a = ba, c = bb;
            #pragma unroll
            for (int k = 0; k < 16; k++) {
                float p = P[L * 16 + k];
                a = fmaf(p, wa[k], a);
                c = fmaf(p, wb[k], c);
            }
            hA[L * 256 + j]       = fmaxf(a, 0.0f);
            hA[L * 256 + j + 128] = fmaxf(c, 0.0f);
        }
    }

    // ---- 3x (256 -> 256) layers; last one writes w2s/cs in smem ----
    const float* Ws[3] = { w0, w1, w_out };
    const float* Bs[3] = { b0, b1, b_out };
    #pragma unroll
    for (int layer = 0; layer < 3; ++layer) {
        const float* hin  = (layer == 1) ? hB : hA;
        float*       hout = (layer == 1) ? hA : hB;
        const float* Wg   = Ws[layer];

        u64 accA[9], accB[9];
        #pragma unroll
        for (int r = 0; r < 9; r++) { accA[r] = 0ull; accB[r] = 0ull; }

        #pragma unroll
        for (int ch = 0; ch < 8; ch++) {
            const int q = layer * 8 + ch;          // global chunk counter
            float* Wcur  = (q & 1) ? WcA : WcB;    // chunk q staged earlier
            float* Wnext = (q & 1) ? WcB : WcA;

            cp_wait<0>();      // my cp.async of chunk q complete
            __syncthreads();   // chunk q visible; prev chunk reads done ->
                               // Wnext overwritable; layer handoff fenced
            if (ch < 7) {
                stage_chunk(Wnext, Wg, (ch + 1) * 32, tid);
                cp_commit();
            } else if (layer < 2) {
                stage_chunk(Wnext, Ws[layer + 1], 0, tid);
                cp_commit();
            }

            const float* hinc = hin + ch * 32;
            #pragma unroll
            for (int k4 = 0; k4 < 8; k4++) {
                ulonglong2 qa = *reinterpret_cast<const ulonglong2*>(
                                    Wcur + j * 36 + k4 * 4);
                ulonglong2 qb = *reinterpret_cast<const ulonglong2*>(
                                    Wcur + (j + 128) * 36 + k4 * 4);
                #pragma unroll
                for (int r = 0; r < 9; r++) {
                    if (r == 8 && g != 1) break;   // uniform per warp
                    int L = (r < 8) ? (8 * g + r) : 16;
                    ulonglong2 qh = *reinterpret_cast<const ulonglong2*>(
                                        hinc + L * 256 + k4 * 4);
                    accA[r] = fma2(qh.x, qa.x, accA[r]);
                    accA[r] = fma2(qh.y, qa.y, accA[r]);
                    accB[r] = fma2(qh.x, qb.x, accB[r]);
                    accB[r] = fma2(qh.y, qb.y, accB[r]);
                }
            }
        }

        float ba = Bs[layer][j];
        float bb = Bs[layer][j + 128];
        if (layer < 2) {
            #pragma unroll
            for (int r = 0; r < 9; r++) {
                if (r == 8 && g != 1) break;
                int L = (r < 8) ? (8 * g + r) : 16;
                float a0, a1; upk(a0, a1, accA[r]);
                float c0, c1; upk(c0, c1, accB[r]);
                hout[L * 256 + j]       = fmaxf(a0 + a1 + ba, 0.0f);
                hout[L * 256 + j + 128] = fmaxf(c0 + c1 + bb, 0.0f);
            }
        } else {
            // neuron j (<128): omega0 = coef*1.5+0.5 -> store omega0^2
            // neuron j+128:    coupling = coef
            #pragma unroll
            for (int r = 0; r < 9; r++) {
                if (r == 8 && g != 1) break;
                int L = (r < 8) ? (8 * g + r) : 16;
                float a0, a1; upk(a0, a1, accA[r]);
                float c0, c1; upk(c0, c1, accB[r]);
                float coefA = a0 + a1 + ba;
                float coefC = c0 + c1 + bb;
                if (L < BM) {
                    float om = fmaf(coefA, 1.5f, 0.5f);
                    w2s[L * 128 + j] = om * om;
                    cs [L * 128 + j] = coefC;
                } else if (j == 127) {
                    cs[-1] = coefC;    // csx: coupling of flat index row0*128-1
                }
            }
        }
    }
    __syncthreads();   // w2s/cs/csx published for the ODE phase

    // ======================= ODE phase =======================
    const float TWO_PI = 6.2831853071795864f;
    const float PI_F   = 3.1415926535897932f;
    const float TEND = 59.0f / 30.0f;       // TS[-1]
    const float H    = TEND / (float)NSTEPS;
    const u64 PH2  = pk(0.5f * H,              0.5f * H);
    const u64 PHH8 = pk(H * H * 0.125f,        H * H * 0.125f);
    const u64 PH   = pk(H,                     H);
    const u64 PHH2 = pk(H * H * 0.5f,          H * H * 0.5f);
    const u64 PHH6 = pk(H * H * (1.0f/6.0f),   H * H * (1.0f/6.0f));
    const u64 PH6  = pk(H * (1.0f/6.0f),       H * (1.0f/6.0f));
    const u64 P2   = pk(2.0f, 2.0f);
    const u64 P4   = pk(4.0f, 4.0f);

    #pragma unroll 1
    for (int pass = 0; pass < 2; pass++) {
        const int r = wid * 2 + pass;           // local row 0..15
        const int ci = r * 128 + lane * 4;

        u64 Y[2], V[2], NW[2], Cc[2], CR[2], NS[2];
        {
            float4 xin = *reinterpret_cast<const float4*>(
                             x + (row0 + r) * XSTRIDE + lane * 4);
            Y[0] = pk(fmaf(xin.x, TWO_PI, -PI_F), fmaf(xin.y, TWO_PI, -PI_F));
            Y[1] = pk(fmaf(xin.z, TWO_PI, -PI_F), fmaf(xin.w, TWO_PI, -PI_F));
            V[0] = 0ull; V[1] = 0ull;

            float4 wv = *reinterpret_cast<const float4*>(w2s + ci);
            NW[0] = pk(-wv.x, -wv.y);
            NW[1] = pk(-wv.z, -wv.w);
            float4 cv = *reinterpret_cast<const float4*>(cs + ci);
            Cc[0] = pk(cv.x, cv.y);
            Cc[1] = pk(cv.z, cv.w);
            float crl = cs[ci - 1];             // flat roll; cs[-1]=csx wrap
            CR[0] = pk(crl,  cv.x);
            CR[1] = pk(cv.y, cv.z);
            NS[0] = pk(-(cv.x + crl),  -(cv.y + cv.x));
            NS[1] = pk(-(cv.z + cv.y), -(cv.w + cv.z));
        }

        #pragma unroll 1
        for (int stp = 0; stp < NSTEPS; ++stp) {
            u64 K1[2], K2[2], K3[2], Y2[2], Y3[2], T[2];
            // k1 = a(Y)
            {
                float y0, y1, y2, y3;
                upk(y0, y1, Y[0]); upk(y2, y3, Y[1]);
                float yl = __shfl_sync(0xffffffffu, y3, (lane + 31) & 31);
                float yr = __shfl_sync(0xffffffffu, y0, (lane + 1) & 31);
                u64 L0 = pk(yl, y0), M = pk(y1, y2), R1 = pk(y3, yr);
                u64 S0 = pk(__sinf(y0), __sinf(y1));
                u64 S1 = pk(__sinf(y2), __sinf(y3));
                u64 a0 = mul2(CR[0], L0);
                a0 = fma2(Cc[0], M, a0); a0 = fma2(NS[0], Y[0], a0);
                a0 = fma2(NW[0], S0, a0);
                u64 a1 = mul2(CR[1], M);
                a1 = fma2(Cc[1], R1, a1); a1 = fma2(NS[1], Y[1], a1);
                a1 = fma2(NW[1], S1, a1);
                K1[0] = a0; K1[1] = a1;
            }
            #pragma unroll
            for (int i = 0; i < 2; i++)
                Y2[i] = fma2(PHH8, K1[i], fma2(PH2, V[i], Y[i]));
            // k2 = a(Y2)
            {
                float y0, y1, y2, y3;
                upk(y0, y1, Y2[0]); upk(y2, y3, Y2[1]);
                float yl = __shfl_sync(0xffffffffu, y3, (lane + 31) & 31);
                float yr = __shfl_sync(0xffffffffu, y0, (lane + 1) & 31);
                u64 L0 = pk(yl, y0), M = pk(y1, y2), R1 = pk(y3, yr);
                u64 S0 = pk(__sinf(y0), __sinf(y1));
                u64 S1 = pk(__sinf(y2), __sinf(y3));
                u64 a0 = mul2(CR[0], L0);
                a0 = fma2(Cc[0], M, a0); a0 = fma2(NS[0], Y2[0], a0);
                a0 = fma2(NW[0], S0, a0);
                u64 a1 = mul2(CR[1], M);
                a1 = fma2(Cc[1], R1, a1); a1 = fma2(NS[1], Y2[1], a1);
                a1 = fma2(NW[1], S1, a1);
                K2[0] = a0; K2[1] = a1;
            }
            #pragma unroll
            for (int i = 0; i < 2; i++) {
                T[i]  = fma2(PH, V[i], Y[i]);
                Y3[i] = fma2(PHH2, K2[i], T[i]);
            }
            // k3 = a(Y3)
            {
                float y0, y1, y2, y3;
                upk(y0, y1, Y3[0]); upk(y2, y3, Y3[1]);
                float yl = __shfl_sync(0xffffffffu, y3, (lane + 31) & 31);
                float yr = __shfl_sync(0xffffffffu, y0, (lane + 1) & 31);
                u64 L0 = pk(yl, y0), M = pk(y1, y2), R1 = pk(y3, yr);
                u64 S0 = pk(__sinf(y0), __sinf(y1));
                u64 S1 = pk(__sinf(y2), __sinf(y3));
                u64 a0 = mul2(CR[0], L0);
                a0 = fma2(Cc[0], M, a0); a0 = fma2(NS[0], Y3[0], a0);
                a0 = fma2(NW[0], S0, a0);
                u64 a1 = mul2(CR[1], M);
                a1 = fma2(Cc[1], R1, a1); a1 = fma2(NS[1], Y3[1], a1);
                a1 = fma2(NW[1], S1, a1);
                K3[0] = a0; K3[1] = a1;
            }
            #pragma unroll
            for (int i = 0; i < 2; i++) {
                Y[i] = fma2(PHH6, fma2(P2, K2[i], K1[i]), T[i]);
                V[i] = fma2(PH6, add2(fma2(P4, K2[i], K1[i]), K3[i]), V[i]);
            }
        }

        float o0, o1, o2, o3;
        upk(o0, o1, Y[0]); upk(o2, o3, Y[1]);
        float4 o;
        o.x = o0 * 0.4f;   // /A_NORM (=2.5), B_NORM=0
        o.y = o1 * 0.4f;
        o.z = o2 * 0.4f;
        o.w = o3 * 0.4f;
        *reinterpret_cast<float4*>(out + (row0 + r) * D + lane * 4) = o;
    }
}

// ============================================================================
extern "C" void kernel_launch(void* const* d_in, const int* in_sizes, int n_in,
                              void* d_out, int out_size)
{
    const float* x     = (const float*)d_in[0];
    const float* w_in  = (const float*)d_in[1];
    const float* b_in  = (const float*)d_in[2];
    const float* w0    = (const float*)d_in[3];
    const float* b0    = (const float*)d_in[4];
    const float* w1    = (const float*)d_in[5];
    const float* b1    = (const float*)d_in[6];
    const float* w_out = (const float*)d_in[7];
    const float* b_out = (const float*)d_in[8];

    cudaFuncSetAttribute(fused_kernel,
                         cudaFuncAttributeMaxDynamicSharedMemorySize,
                         SMEM_BYTES);
    fused_kernel<<<BATCH / BM, TPB, SMEM_BYTES>>>(
        x, w_in, b_in, w0, b0, w1, b1, w_out, b_out, (float*)d_out);
}

// round 13
// speedup vs baseline: 1.5968x; 1.5968x over previous
#include <cuda_runtime.h>
#include <cuda_bf16.h>
#include <cstdint>

#define BATCH   4096
#define D       128
#define NP      16
#define HID     256
#define XSTRIDE 144           // D + NPARAMS
#define NTOT    (BATCH * D)   // 524288 = 2^19
#define NMASK   (NTOT - 1)
#define NSTEPS  8             // validated R9: rel_err 1.4376e-4 at N=8

typedef unsigned long long u64;
typedef unsigned int       u32;

// ---------------- packed f32x2 helpers (used by ODE only) ----------------
__device__ __forceinline__ u64 pk(float lo, float hi) {
    u64 r; asm("mov.b64 %0, {%1, %2};" : "=l"(r) : "f"(lo), "f"(hi)); return r;
}
__device__ __forceinline__ void upk(float& lo, float& hi, u64 v) {
    asm("mov.b64 {%0, %1}, %2;" : "=f"(lo), "=f"(hi) : "l"(v));
}
__device__ __forceinline__ u64 fma2(u64 a, u64 b, u64 c) {
    u64 r; asm("fma.rn.f32x2 %0, %1, %2, %3;" : "=l"(r) : "l"(a), "l"(b), "l"(c)); return r;
}
__device__ __forceinline__ u64 mul2(u64 a, u64 b) {
    u64 r; asm("mul.rn.f32x2 %0, %1, %2;" : "=l"(r) : "l"(a), "l"(b)); return r;
}
__device__ __forceinline__ u64 add2(u64 a, u64 b) {
    u64 r; asm("add.rn.f32x2 %0, %1, %2;" : "=l"(r) : "l"(a), "l"(b)); return r;
}

// ---------------- cp.async helpers ----------------
__device__ __forceinline__ u32 smem_u32(const void* p) {
    return (u32)__cvta_generic_to_shared(p);
}
__device__ __forceinline__ void cp16(void* dst, const void* src) {
    asm volatile("cp.async.cg.shared.global [%0], [%1], 16;\n"
                 :: "r"(smem_u32(dst)), "l"(src));
}
__device__ __forceinline__ void cp_commit() {
    asm volatile("cp.async.commit_group;\n");
}
template<int N> __device__ __forceinline__ void cp_wait() {
    asm volatile("cp.async.wait_group %0;\n" :: "n"(N));
}

// ---------------- mma.sync bf16 (sm_80+, works on sm_100 base target) ------
__device__ __forceinline__ void mma_bf16(float* d, const u32* a, const u32* b) {
    asm volatile(
        "mma.sync.aligned.m16n8k16.row.col.f32.bf16.bf16.f32 "
        "{%0,%1,%2,%3}, {%4,%5,%6,%7}, {%8,%9}, {%0,%1,%2,%3};"
        : "+f"(d[0]), "+f"(d[1]), "+f"(d[2]), "+f"(d[3])
        : "r"(a[0]), "r"(a[1]), "r"(a[2]), "r"(a[3]), "r"(b[0]), "r"(b[1]));
}

// ---------------- global scratch (allocation-free contract) ----------------
__device__ __align__(16) __nv_bfloat16 g_Whi[3][HID * HID];
__device__ __align__(16) __nv_bfloat16 g_Wlo[3][HID * HID];
__device__ __align__(16) __nv_bfloat16 g_Ahi[2][BATCH * HID];
__device__ __align__(16) __nv_bfloat16 g_Alo[2][BATCH * HID];
__device__ __align__(16) float g_w2[NTOT];   // omega0^2 [row][128]
__device__ __align__(16) float g_c [NTOT];   // coupling [row][128]

// ============================================================================
// prep kernel: blocks 0..127 = input layer (16->256, relu, bf16 hi/lo split);
//              blocks 128..191 = weight conversion f32 -> bf16 hi/lo.
// ============================================================================
__global__ void __launch_bounds__(256) prep_kernel(
    const float* __restrict__ x,
    const float* __restrict__ w_in, const float* __restrict__ b_in,
    const float* __restrict__ w0,   const float* __restrict__ w1,
    const float* __restrict__ w_out)
{
    const int tid = threadIdx.x;
    const int bid = blockIdx.x;
    if (bid < 128) {
        __shared__ float Wc[HID * 17];
        __shared__ float P[32 * 16];
        const int row0 = bid * 32;
        for (int idx = tid; idx < 32 * NP; idx += 256) {
            int r = idx >> 4, k = idx & 15;
            P[idx] = x[(row0 + r) * XSTRIDE + D + k];
        }
        for (int idx = tid; idx < HID * NP; idx += 256) {
            int j = idx >> 4, k = idx & 15;
            Wc[j * 17 + k] = w_in[idx];
        }
        __syncthreads();
        float w[16];
        #pragma unroll
        for (int k = 0; k < 16; k++) w[k] = Wc[tid * 17 + k];
        const float b = b_in[tid];
        #pragma unroll 1
        for (int r = 0; r < 32; r++) {
            float acc = b;
            #pragma unroll
            for (int k = 0; k < 16; k++) acc = fmaf(P[r * 16 + k], w[k], acc);
            float h = fmaxf(acc, 0.0f);
            __nv_bfloat16 hi = __float2bfloat16(h);
            float lo = h - __bfloat162float(hi);
            g_Ahi[0][(size_t)(row0 + r) * HID + tid] = hi;
            g_Alo[0][(size_t)(row0 + r) * HID + tid] = __float2bfloat16(lo);
        }
    } else {
        const float* Ws[3] = { w0, w1, w_out };
        const int t = (bid - 128) * 256 + tid;   // 0..16383
        #pragma unroll 1
        for (int i = 0; i < 12; i++) {
            int e = t + i * 16384;               // < 196608 = 3*65536
            int L = e >> 16;
            int rem = e & 65535;
            float wv = Ws[L][rem];
            __nv_bfloat16 hi = __float2bfloat16(wv);
            g_Whi[L][rem] = hi;
            g_Wlo[L][rem] = __float2bfloat16(wv - __bfloat162float(hi));
        }
    }
}

// ============================================================================
// GEMM kernel (mma.sync m16n8k16 bf16, 3-split hi/lo).
// Grid 128 = 64 M-tiles (64 rows) x 2 N-halves (128 cols). 256 threads,
// 8 warps in 2x4: warp computes 32x32 (2 m16-tiles x 4 n8-tiles).
// K staged in 64-wide chunks, rows padded to 72 elements (144 B = 4 banks
// mod 32 -> the 8-row x 16B fragment pattern is bank-conflict-free).
// Double-buffered cp.async; one __syncthreads per chunk.
// smem per buffer: Ahi 64x72 | Alo | Whi 128x72 | Wlo  = 55296 B; x2 buffers.
// ============================================================================
#define BUF_BYTES 55296
#define AOFF_LO   9216
#define WOFF_HI   18432
#define WOFF_LO   36864
#define GEMM_SMEM (2 * BUF_BYTES)    // 110592 B

__device__ __forceinline__ void stage_rows(char* dst, const __nv_bfloat16* __restrict__ src,
                                           int row_g0, int nrows, int kc, int tid)
{
    for (int i = tid; i < nrows * 8; i += 256) {
        int row = i >> 3, g = i & 7;
        cp16(dst + row * 144 + g * 16,
             src + (size_t)(row_g0 + row) * HID + kc + g * 8);
    }
}

__global__ void __launch_bounds__(256) gemm_kernel(
    int layer, int inb, int outb, const float* __restrict__ bias)
{
    extern __shared__ char sm[];
    const int tid   = threadIdx.x;
    const int wid   = tid >> 5;
    const int lane  = tid & 31;
    const int gid   = lane >> 2;       // fragment group (row within 8)
    const int t4    = lane & 3;        // thread-in-group (col pair)
    const int wm    = wid >> 2;        // warp m index (0..1)
    const int wn    = wid & 3;         // warp n index (0..3)
    const int mtile = blockIdx.x >> 1;
    const int nhalf = blockIdx.x & 1;
    const int row0  = mtile * 64;
    const int n0    = nhalf * 128;

    const __nv_bfloat16* Ahi = g_Ahi[inb];
    const __nv_bfloat16* Alo = g_Alo[inb];
    const __nv_bfloat16* Bhi = g_Whi[layer];
    const __nv_bfloat16* Blo = g_Wlo[layer];

    float acc[2][4][4];
    #pragma unroll
    for (int mt = 0; mt < 2; mt++)
        #pragma unroll
        for (int nt = 0; nt < 4; nt++)
            #pragma unroll
            for (int e = 0; e < 4; e++) acc[mt][nt][e] = 0.0f;

    // stage chunk 0 into buffer 0
    stage_rows(sm +           0, Ahi, row0, 64,  0, tid);
    stage_rows(sm +     AOFF_LO, Alo, row0, 64,  0, tid);
    stage_rows(sm +     WOFF_HI, Bhi, n0,  128,  0, tid);
    stage_rows(sm +     WOFF_LO, Blo, n0,  128,  0, tid);
    cp_commit();

    #pragma unroll 1
    for (int q = 0; q < 4; q++) {
        cp_wait<0>();
        __syncthreads();   // chunk q visible; chunk q-1 compute done (its
                           // buffer is the one about to be restaged)
        if (q < 3) {
            char* nxt = sm + ((q + 1) & 1) * BUF_BYTES;
            int kc = (q + 1) * 64;
            stage_rows(nxt +       0, Ahi, row0, 64,  kc, tid);
            stage_rows(nxt + AOFF_LO, Alo, row0, 64,  kc, tid);
            stage_rows(nxt + WOFF_HI, Bhi, n0,  128,  kc, tid);
            stage_rows(nxt + WOFF_LO, Blo, n0,  128,  kc, tid);
            cp_commit();
        }

        const char* cb = sm + (q & 1) * BUF_BYTES;
        const __nv_bfloat16* Ah = (const __nv_bfloat16*)(cb);
        const __nv_bfloat16* Al = (const __nv_bfloat16*)(cb + AOFF_LO);
        const __nv_bfloat16* Wh = (const __nv_bfloat16*)(cb + WOFF_HI);
        const __nv_bfloat16* Wl = (const __nv_bfloat16*)(cb + WOFF_LO);

        #pragma unroll
        for (int ks = 0; ks < 4; ks++) {
            const int kb = ks * 16;
            u32 aH[2][4], aL[2][4], bH[4][2], bL[4][2];
            #pragma unroll
            for (int mt = 0; mt < 2; mt++) {
                int r0 = wm * 32 + mt * 16 + gid;
                int c0 = kb + 2 * t4;
                aH[mt][0] = *(const u32*)(Ah + (r0)     * 72 + c0);
                aH[mt][1] = *(const u32*)(Ah + (r0 + 8) * 72 + c0);
                aH[mt][2] = *(const u32*)(Ah + (r0)     * 72 + c0 + 8);
                aH[mt][3] = *(const u32*)(Ah + (r0 + 8) * 72 + c0 + 8);
                aL[mt][0] = *(const u32*)(Al + (r0)     * 72 + c0);
                aL[mt][1] = *(const u32*)(Al + (r0 + 8) * 72 + c0);
                aL[mt][2] = *(const u32*)(Al + (r0)     * 72 + c0 + 8);
                aL[mt][3] = *(const u32*)(Al + (r0 + 8) * 72 + c0 + 8);
            }
            #pragma unroll
            for (int nt = 0; nt < 4; nt++) {
                int nr = wn * 32 + nt * 8 + gid;
                int c0 = kb + 2 * t4;
                bH[nt][0] = *(const u32*)(Wh + nr * 72 + c0);
                bH[nt][1] = *(const u32*)(Wh + nr * 72 + c0 + 8);
                bL[nt][0] = *(const u32*)(Wl + nr * 72 + c0);
                bL[nt][1] = *(const u32*)(Wl + nr * 72 + c0 + 8);
            }
            #pragma unroll
            for (int mt = 0; mt < 2; mt++)
                #pragma unroll
                for (int nt = 0; nt < 4; nt++) {
                    mma_bf16(acc[mt][nt], aH[mt], bH[nt]);   // hi*hi
                    mma_bf16(acc[mt][nt], aH[mt], bL[nt]);   // hi*lo
                    mma_bf16(acc[mt][nt], aL[mt], bH[nt]);   // lo*hi
                }
        }
    }

    // ---------------- epilogue (register-only; no sync needed) -------------
    #pragma unroll
    for (int mt = 0; mt < 2; mt++) {
        #pragma unroll
        for (int nt = 0; nt < 4; nt++) {
            const int m  = row0 + wm * 32 + mt * 16 + gid;
            const int n  = n0 + wn * 32 + nt * 8 + 2 * t4;
            const float b0v = bias[n];
            const float b1v = bias[n + 1];
            const float* a = acc[mt][nt];
            if (layer < 2) {
                #pragma unroll
                for (int rr = 0; rr < 2; rr++) {
                    const int mr = m + rr * 8;
                    float v0 = fmaxf(a[2 * rr]     + b0v, 0.0f);
                    float v1 = fmaxf(a[2 * rr + 1] + b1v, 0.0f);
                    __nv_bfloat16 h0 = __float2bfloat16(v0);
                    __nv_bfloat16 h1 = __float2bfloat16(v1);
                    __nv_bfloat162 hh; hh.x = h0; hh.y = h1;
                    __nv_bfloat162 ll;
                    ll.x = __float2bfloat16(v0 - __bfloat162float(h0));
                    ll.y = __float2bfloat16(v1 - __bfloat162float(h1));
                    *(u32*)(g_Ahi[outb] + (size_t)mr * HID + n) = *(u32*)&hh;
                    *(u32*)(g_Alo[outb] + (size_t)mr * HID + n) = *(u32*)&ll;
                }
            } else {
                const int nloc = n & 127;
                #pragma unroll
                for (int rr = 0; rr < 2; rr++) {
                    const int mr = m + rr * 8;
                    float c0 = a[2 * rr]     + b0v;
                    float c1 = a[2 * rr + 1] + b1v;
                    float2 v;
                    if (nhalf == 0) {
                        float o0 = fmaf(c0, 1.5f, 0.5f);
                        float o1 = fmaf(c1, 1.5f, 0.5f);
                        v = make_float2(o0 * o0, o1 * o1);
                        *(float2*)(g_w2 + (size_t)mr * D + nloc) = v;
                    } else {
                        v = make_float2(c0, c1);
                        *(float2*)(g_c + (size_t)mr * D + nloc) = v;
                    }
                }
            }
        }
    }
}

// ============================================================================
// ODE: one warp per batch row (128-ring), 4 elems/thread, RKN4 (3 evals/step).
// ============================================================================
__device__ __forceinline__ void accel2(const u64 Y[2], const u64 NW[2],
                                       const u64 C[2],  const u64 CR[2],
                                       const u64 NS[2], int lane, u64 A[2])
{
    float y0, y1, y2, y3;
    upk(y0, y1, Y[0]); upk(y2, y3, Y[1]);
    float yl = __shfl_sync(0xffffffffu, y3, (lane + 31) & 31);
    float yr = __shfl_sync(0xffffffffu, y0, (lane + 1) & 31);
    u64 L0 = pk(yl, y0);
    u64 M  = pk(y1, y2);
    u64 R1 = pk(y3, yr);
    u64 S0 = pk(__sinf(y0), __sinf(y1));
    u64 S1 = pk(__sinf(y2), __sinf(y3));
    u64 a0 = mul2(CR[0], L0);
    a0 = fma2(C[0],  M,    a0);
    a0 = fma2(NS[0], Y[0], a0);
    a0 = fma2(NW[0], S0,   a0);
    u64 a1 = mul2(CR[1], M);
    a1 = fma2(C[1],  R1,   a1);
    a1 = fma2(NS[1], Y[1], a1);
    a1 = fma2(NW[1], S1,   a1);
    A[0] = a0; A[1] = a1;
}

__global__ void __launch_bounds__(128) ode_kernel(const float* __restrict__ x,
                                                  float* __restrict__ out)
{
    const int gtid = blockIdx.x * 128 + threadIdx.x;
    const int b    = gtid >> 5;
    const int lane = threadIdx.x & 31;
    const int base = b * D + lane * 4;

    const float TWO_PI = 6.2831853071795864f;
    const float PI_F   = 3.1415926535897932f;

    u64 Y[2], V[2], NW[2], Cc[2], CR[2], NS[2];
    {
        float4 xin = *reinterpret_cast<const float4*>(x + b * XSTRIDE + lane * 4);
        Y[0] = pk(fmaf(xin.x, TWO_PI, -PI_F), fmaf(xin.y, TWO_PI, -PI_F));
        Y[1] = pk(fmaf(xin.z, TWO_PI, -PI_F), fmaf(xin.w, TWO_PI, -PI_F));
        V[0] = 0ull; V[1] = 0ull;

        float4 wv = *reinterpret_cast<const float4*>(g_w2 + base);
        NW[0] = pk(-wv.x, -wv.y);
        NW[1] = pk(-wv.z, -wv.w);
        float4 cv = *reinterpret_cast<const float4*>(g_c + base);
        Cc[0] = pk(cv.x, cv.y);
        Cc[1] = pk(cv.z, cv.w);
        float crl = g_c[(base - 1) & NMASK];   // flat roll crosses rows
        CR[0] = pk(crl,  cv.x);
        CR[1] = pk(cv.y, cv.z);
        NS[0] = pk(-(cv.x + crl),  -(cv.y + cv.x));
        NS[1] = pk(-(cv.z + cv.y), -(cv.w + cv.z));
    }

    const float TEND = 59.0f / 30.0f;
    const float H    = TEND / (float)NSTEPS;
    const u64 PH2  = pk(0.5f * H,              0.5f * H);
    const u64 PHH8 = pk(H * H * 0.125f,        H * H * 0.125f);
    const u64 PH   = pk(H,                     H);
    const u64 PHH2 = pk(H * H * 0.5f,          H * H * 0.5f);
    const u64 PHH6 = pk(H * H * (1.0f/6.0f),   H * H * (1.0f/6.0f));
    const u64 PH6  = pk(H * (1.0f/6.0f),       H * (1.0f/6.0f));
    const u64 P2   = pk(2.0f, 2.0f);
    const u64 P4   = pk(4.0f, 4.0f);

    #pragma unroll 1
    for (int stp = 0; stp < NSTEPS; ++stp) {
        u64 K1[2], K2[2], K3[2], Y2[2], Y3[2], T[2];
        accel2(Y, NW, Cc, CR, NS, lane, K1);
        #pragma unroll
        for (int i = 0; i < 2; i++)
            Y2[i] = fma2(PHH8, K1[i], fma2(PH2, V[i], Y[i]));
        accel2(Y2, NW, Cc, CR, NS, lane, K2);
        #pragma unroll
        for (int i = 0; i < 2; i++) {
            T[i]  = fma2(PH, V[i], Y[i]);
            Y3[i] = fma2(PHH2, K2[i], T[i]);
        }
        accel2(Y3, NW, Cc, CR, NS, lane, K3);
        #pragma unroll
        for (int i = 0; i < 2; i++) {
            Y[i] = fma2(PHH6, fma2(P2, K2[i], K1[i]), T[i]);
            V[i] = fma2(PH6, add2(fma2(P4, K2[i], K1[i]), K3[i]), V[i]);
        }
    }

    float o0, o1, o2, o3;
    upk(o0, o1, Y[0]); upk(o2, o3, Y[1]);
    float4 o;
    o.x = o0 * 0.4f;   // /A_NORM (=2.5), B_NORM=0
    o.y = o1 * 0.4f;
    o.z = o2 * 0.4f;
    o.w = o3 * 0.4f;
    *reinterpret_cast<float4*>(out + base) = o;
}

// ============================================================================
extern "C" void kernel_launch(void* const* d_in, const int* in_sizes, int n_in,
                              void* d_out, int out_size)
{
    const float* x     = (const float*)d_in[0];
    const float* w_in  = (const float*)d_in[1];
    const float* b_in  = (const float*)d_in[2];
    const float* w0    = (const float*)d_in[3];
    const float* b0    = (const float*)d_in[4];
    const float* w1    = (const float*)d_in[5];
    const float* b1    = (const float*)d_in[6];
    const float* w_out = (const float*)d_in[7];
    const float* b_out = (const float*)d_in[8];

    cudaFuncSetAttribute(gemm_kernel,
                         cudaFuncAttributeMaxDynamicSharedMemorySize, GEMM_SMEM);

    prep_kernel<<<192, 256>>>(x, w_in, b_in, w0, w1, w_out);
    gemm_kernel<<<128, 256, GEMM_SMEM>>>(0, 0, 1, b0);     // A0 -> A1
    gemm_kernel<<<128, 256, GEMM_SMEM>>>(1, 1, 0, b1);     // A1 -> A0
    gemm_kernel<<<128, 256, GEMM_SMEM>>>(2, 0, 0, b_out);  // A0 -> g_w2/g_c
    ode_kernel<<<(BATCH * 32) / 128, 128>>>(x, (float*)d_out);
}

// round 15
// speedup vs baseline: 1.6818x; 1.0533x over previous
#include <cuda_runtime.h>
#include <cuda_bf16.h>
#include <cstdint>

#define BATCH   4096
#define D       128
#define NP      16
#define HID     256
#define XSTRIDE 144           // D + NPARAMS
#define NTOT    (BATCH * D)   // 524288 = 2^19
#define NMASK   (NTOT - 1)
#define NSTEPS  8             // validated R9/R13: rel_err ~1.44e-4 at N=8

typedef unsigned long long u64;
typedef unsigned int       u32;

// ---------------- packed f32x2 helpers (used by ODE only) ----------------
__device__ __forceinline__ u64 pk(float lo, float hi) {
    u64 r; asm("mov.b64 %0, {%1, %2};" : "=l"(r) : "f"(lo), "f"(hi)); return r;
}
__device__ __forceinline__ void upk(float& lo, float& hi, u64 v) {
    asm("mov.b64 {%0, %1}, %2;" : "=f"(lo), "=f"(hi) : "l"(v));
}
__device__ __forceinline__ u64 fma2(u64 a, u64 b, u64 c) {
    u64 r; asm("fma.rn.f32x2 %0, %1, %2, %3;" : "=l"(r) : "l"(a), "l"(b), "l"(c)); return r;
}
__device__ __forceinline__ u64 mul2(u64 a, u64 b) {
    u64 r; asm("mul.rn.f32x2 %0, %1, %2;" : "=l"(r) : "l"(a), "l"(b)); return r;
}
__device__ __forceinline__ u64 add2(u64 a, u64 b) {
    u64 r; asm("add.rn.f32x2 %0, %1, %2;" : "=l"(r) : "l"(a), "l"(b)); return r;
}

// ---------------- cp.async helpers ----------------
__device__ __forceinline__ u32 smem_u32(const void* p) {
    return (u32)__cvta_generic_to_shared(p);
}
__device__ __forceinline__ void cp16(void* dst, const void* src) {
    asm volatile("cp.async.cg.shared.global [%0], [%1], 16;\n"
                 :: "r"(smem_u32(dst)), "l"(src));
}
__device__ __forceinline__ void cp_commit() {
    asm volatile("cp.async.commit_group;\n");
}
template<int N> __device__ __forceinline__ void cp_wait() {
    asm volatile("cp.async.wait_group %0;\n" :: "n"(N));
}

// ---------------- mma.sync bf16 + ldmatrix (sm_80+/sm_75+) ----------------
__device__ __forceinline__ void mma_bf16(float* d, const u32* a, const u32* b) {
    asm volatile(
        "mma.sync.aligned.m16n8k16.row.col.f32.bf16.bf16.f32 "
        "{%0,%1,%2,%3}, {%4,%5,%6,%7}, {%8,%9}, {%0,%1,%2,%3};"
        : "+f"(d[0]), "+f"(d[1]), "+f"(d[2]), "+f"(d[3])
        : "r"(a[0]), "r"(a[1]), "r"(a[2]), "r"(a[3]), "r"(b[0]), "r"(b[1]));
}
__device__ __forceinline__ void ldsm4(u32& r0, u32& r1, u32& r2, u32& r3, u32 addr) {
    asm volatile("ldmatrix.sync.aligned.m8n8.x4.shared.b16 {%0,%1,%2,%3}, [%4];"
                 : "=r"(r0), "=r"(r1), "=r"(r2), "=r"(r3) : "r"(addr));
}

// ---------------- global scratch (allocation-free contract) ----------------
__device__ __align__(16) __nv_bfloat16 g_Whi[3][HID * HID];
__device__ __align__(16) __nv_bfloat16 g_Wlo[3][HID * HID];
__device__ __align__(16) __nv_bfloat16 g_Ahi[2][BATCH * HID];
__device__ __align__(16) __nv_bfloat16 g_Alo[2][BATCH * HID];
__device__ __align__(16) float g_w2[NTOT];   // omega0^2 [row][128]
__device__ __align__(16) float g_c [NTOT];   // coupling [row][128]

// ============================================================================
// prep kernel (unchanged from R13): input layer + weight hi/lo conversion.
// ============================================================================
__global__ void __launch_bounds__(256) prep_kernel(
    const float* __restrict__ x,
    const float* __restrict__ w_in, const float* __restrict__ b_in,
    const float* __restrict__ w0,   const float* __restrict__ w1,
    const float* __restrict__ w_out)
{
    const int tid = threadIdx.x;
    const int bid = blockIdx.x;
    if (bid < 128) {
        __shared__ float Wc[HID * 17];
        __shared__ float P[32 * 16];
        const int row0 = bid * 32;
        for (int idx = tid; idx < 32 * NP; idx += 256) {
            int r = idx >> 4, k = idx & 15;
            P[idx] = x[(row0 + r) * XSTRIDE + D + k];
        }
        for (int idx = tid; idx < HID * NP; idx += 256) {
            int j = idx >> 4, k = idx & 15;
            Wc[j * 17 + k] = w_in[idx];
        }
        __syncthreads();
        float w[16];
        #pragma unroll
        for (int k = 0; k < 16; k++) w[k] = Wc[tid * 17 + k];
        const float b = b_in[tid];
        #pragma unroll 1
        for (int r = 0; r < 32; r++) {
            float acc = b;
            #pragma unroll
            for (int k = 0; k < 16; k++) acc = fmaf(P[r * 16 + k], w[k], acc);
            float h = fmaxf(acc, 0.0f);
            __nv_bfloat16 hi = __float2bfloat16(h);
            float lo = h - __bfloat162float(hi);
            g_Ahi[0][(size_t)(row0 + r) * HID + tid] = hi;
            g_Alo[0][(size_t)(row0 + r) * HID + tid] = __float2bfloat16(lo);
        }
    } else {
        const float* Ws[3] = { w0, w1, w_out };
        const int t = (bid - 128) * 256 + tid;   // 0..16383
        #pragma unroll 1
        for (int i = 0; i < 12; i++) {
            int e = t + i * 16384;               // < 196608 = 3*65536
            int L = e >> 16;
            int rem = e & 65535;
            float wv = Ws[L][rem];
            __nv_bfloat16 hi = __float2bfloat16(wv);
            g_Whi[L][rem] = hi;
            g_Wlo[L][rem] = __float2bfloat16(wv - __bfloat162float(hi));
        }
    }
}

// ============================================================================
// GEMM kernel: mma.sync m16n8k16 bf16 3-split, ldmatrix fragment loads,
// ALL 4 K-chunks staged upfront (4 commit groups), gated by cp_wait<3-q>.
// Grid 128 = 64 M-tiles (64 rows) x 2 N-halves. 256 threads, 8 warps (2x4),
// warp = 32x32 output. Rows padded to 72 elements (144 B): ldmatrix's 8-row
// x 16B footprint covers all 32 banks exactly once (stride = 4 banks/row).
// ============================================================================
#define CHUNK_BYTES 55296            // Ahi 64x144 | Alo | Whi 128x144 | Wlo
#define AOFF_LO   9216
#define WOFF_HI   18432
#define WOFF_LO   36864
#define GEMM_SMEM (4 * CHUNK_BYTES)  // 221184 B

__device__ __forceinline__ void stage_rows(char* dst, const __nv_bfloat16* __restrict__ src,
                                           int row_g0, int nrows, int kc, int tid)
{
    for (int i = tid; i < nrows * 8; i += 256) {
        int row = i >> 3, g = i & 7;
        cp16(dst + row * 144 + g * 16,
             src + (size_t)(row_g0 + row) * HID + kc + g * 8);
    }
}

__global__ void __launch_bounds__(256) gemm_kernel(
    int layer, int inb, int outb, const float* __restrict__ bias)
{
    extern __shared__ char sm[];
    const int tid   = threadIdx.x;
    const int wid   = tid >> 5;
    const int lane  = tid & 31;
    const int gid   = lane >> 2;       // fragment group (row within 8)
    const int t4    = lane & 3;        // thread-in-group (col pair)
    const int wm    = wid >> 2;        // warp m index (0..1)
    const int wn    = wid & 3;         // warp n index (0..3)
    const int mtile = blockIdx.x >> 1;
    const int nhalf = blockIdx.x & 1;
    const int row0  = mtile * 64;
    const int n0    = nhalf * 128;

    const __nv_bfloat16* Ahi = g_Ahi[inb];
    const __nv_bfloat16* Alo = g_Alo[inb];
    const __nv_bfloat16* Bhi = g_Whi[layer];
    const __nv_bfloat16* Blo = g_Wlo[layer];

    // ---- stage ALL 4 chunks upfront, one commit group per chunk ----
    #pragma unroll
    for (int q = 0; q < 4; q++) {
        char* c = sm + q * CHUNK_BYTES;
        const int kc = q * 64;
        stage_rows(c +       0, Ahi, row0, 64,  kc, tid);
        stage_rows(c + AOFF_LO, Alo, row0, 64,  kc, tid);
        stage_rows(c + WOFF_HI, Bhi, n0,  128,  kc, tid);
        stage_rows(c + WOFF_LO, Blo, n0,  128,  kc, tid);
        cp_commit();
    }

    // ---- per-lane ldmatrix base offsets (byte offsets within regions) ----
    // A 16x16 tile, x4 tile order: T0=(m0-7,k0-7) T1=(m8-15,k0-7)
    //                              T2=(m0-7,k8-15) T3=(m8-15,k8-15)
    //   lane tile lt = lane>>3: row += (lt&1)*8, col += (lt>>1)*8
    // B x4 covers ntile pair: T0=(ntE,k0-7) T1=(ntE,k8-15) T2=(ntO,k0-7) T3=(ntO,k8-15)
    //   row += (lt>>1)*8 (odd ntile), col += (lt&1)*8
    const int l8 = lane & 7, lt = lane >> 3;
    const u32 sbase = smem_u32(sm);
    const u32 aOff = (u32)((wm * 32 + (lt & 1) * 8 + l8) * 144 + ((lt >> 1) * 8) * 2);
    const u32 bOff = (u32)((wn * 32 + (lt >> 1) * 8 + l8) * 144 + ((lt & 1) * 8) * 2);

    float acc[2][4][4];
    #pragma unroll
    for (int mt = 0; mt < 2; mt++)
        #pragma unroll
        for (int nt = 0; nt < 4; nt++)
            #pragma unroll
            for (int e = 0; e < 4; e++) acc[mt][nt][e] = 0.0f;

    #pragma unroll
    for (int q = 0; q < 4; q++) {
        if      (q == 0) cp_wait<3>();
        else if (q == 1) cp_wait<2>();
        else if (q == 2) cp_wait<1>();
        else             cp_wait<0>();
        __syncthreads();   // all threads waited -> chunk q fully visible

        const u32 cb = sbase + (u32)q * CHUNK_BYTES;
        #pragma unroll
        for (int ks = 0; ks < 4; ks++) {
            const u32 kb = (u32)ks * 32;   // 16 elems * 2B
            u32 aH[2][4], aL[2][4], bH[8], bL[8];
            #pragma unroll
            for (int mt = 0; mt < 2; mt++) {
                u32 ad = cb + aOff + (u32)(mt * 16 * 144) + kb;
                ldsm4(aH[mt][0], aH[mt][1], aH[mt][2], aH[mt][3], ad);
                ldsm4(aL[mt][0], aL[mt][1], aL[mt][2], aL[mt][3], ad + AOFF_LO);
            }
            #pragma unroll
            for (int p = 0; p < 2; p++) {   // ntile pairs (0,1) and (2,3)
                u32 bd = cb + WOFF_HI + bOff + (u32)(p * 16 * 144) + kb;
                ldsm4(bH[4 * p], bH[4 * p + 1], bH[4 * p + 2], bH[4 * p + 3], bd);
                ldsm4(bL[4 * p], bL[4 * p + 1], bL[4 * p + 2], bL[4 * p + 3],
                      bd + (WOFF_LO - WOFF_HI));
            }
            #pragma unroll
            for (int mt = 0; mt < 2; mt++)
                #pragma unroll
                for (int nt = 0; nt < 4; nt++) {
                    mma_bf16(acc[mt][nt], aH[mt], bH + 2 * nt);   // hi*hi
                    mma_bf16(acc[mt][nt], aH[mt], bL + 2 * nt);   // hi*lo
                    mma_bf16(acc[mt][nt], aL[mt], bH + 2 * nt);   // lo*hi
                }
        }
    }

    // ---------------- epilogue (register-only; unchanged from R13) ---------
    #pragma unroll
    for (int mt = 0; mt < 2; mt++) {
        #pragma unroll
        for (int nt = 0; nt < 4; nt++) {
            const int m  = row0 + wm * 32 + mt * 16 + gid;
            const int n  = n0 + wn * 32 + nt * 8 + 2 * t4;
            const float b0v = bias[n];
            const float b1v = bias[n + 1];
            const float* a = acc[mt][nt];
            if (layer < 2) {
                #pragma unroll
                for (int rr = 0; rr < 2; rr++) {
                    const int mr = m + rr * 8;
                    float v0 = fmaxf(a[2 * rr]     + b0v, 0.0f);
                    float v1 = fmaxf(a[2 * rr + 1] + b1v, 0.0f);
                    __nv_bfloat16 h0 = __float2bfloat16(v0);
                    __nv_bfloat16 h1 = __float2bfloat16(v1);
                    __nv_bfloat162 hh; hh.x = h0; hh.y = h1;
                    __nv_bfloat162 ll;
                    ll.x = __float2bfloat16(v0 - __bfloat162float(h0));
                    ll.y = __float2bfloat16(v1 - __bfloat162float(h1));
                    *(u32*)(g_Ahi[outb] + (size_t)mr * HID + n) = *(u32*)&hh;
                    *(u32*)(g_Alo[outb] + (size_t)mr * HID + n) = *(u32*)&ll;
                }
            } else {
                const int nloc = n & 127;
                #pragma unroll
                for (int rr = 0; rr < 2; rr++) {
                    const int mr = m + rr * 8;
                    float c0 = a[2 * rr]     + b0v;
                    float c1 = a[2 * rr + 1] + b1v;
                    float2 v;
                    if (nhalf == 0) {
                        float o0 = fmaf(c0, 1.5f, 0.5f);
                        float o1 = fmaf(c1, 1.5f, 0.5f);
                        v = make_float2(o0 * o0, o1 * o1);
                        *(float2*)(g_w2 + (size_t)mr * D + nloc) = v;
                    } else {
                        v = make_float2(c0, c1);
                        *(float2*)(g_c + (size_t)mr * D + nloc) = v;
                    }
                }
            }
        }
    }
}

// ============================================================================
// ODE: one warp per batch row (128-ring), 4 elems/thread, RKN4 (3 evals/step).
// ============================================================================
__device__ __forceinline__ void accel2(const u64 Y[2], const u64 NW[2],
                                       const u64 C[2],  const u64 CR[2],
                                       const u64 NS[2], int lane, u64 A[2])
{
    float y0, y1, y2, y3;
    upk(y0, y1, Y[0]); upk(y2, y3, Y[1]);
    float yl = __shfl_sync(0xffffffffu, y3, (lane + 31) & 31);
    float yr = __shfl_sync(0xffffffffu, y0, (lane + 1) & 31);
    u64 L0 = pk(yl, y0);
    u64 M  = pk(y1, y2);
    u64 R1 = pk(y3, yr);
    u64 S0 = pk(__sinf(y0), __sinf(y1));
    u64 S1 = pk(__sinf(y2), __sinf(y3));
    u64 a0 = mul2(CR[0], L0);
    a0 = fma2(C[0],  M,    a0);
    a0 = fma2(NS[0], Y[0], a0);
    a0 = fma2(NW[0], S0,   a0);
    u64 a1 = mul2(CR[1], M);
    a1 = fma2(C[1],  R1,   a1);
    a1 = fma2(NS[1], Y[1], a1);
    a1 = fma2(NW[1], S1,   a1);
    A[0] = a0; A[1] = a1;
}

__global__ void __launch_bounds__(128) ode_kernel(const float* __restrict__ x,
                                                  float* __restrict__ out)
{
    const int gtid = blockIdx.x * 128 + threadIdx.x;
    const int b    = gtid >> 5;
    const int lane = threadIdx.x & 31;
    const int base = b * D + lane * 4;

    const float TWO_PI = 6.2831853071795864f;
    const float PI_F   = 3.1415926535897932f;

    u64 Y[2], V[2], NW[2], Cc[2], CR[2], NS[2];
    {
        float4 xin = *reinterpret_cast<const float4*>(x + b * XSTRIDE + lane * 4);
        Y[0] = pk(fmaf(xin.x, TWO_PI, -PI_F), fmaf(xin.y, TWO_PI, -PI_F));
        Y[1] = pk(fmaf(xin.z, TWO_PI, -PI_F), fmaf(xin.w, TWO_PI, -PI_F));
        V[0] = 0ull; V[1] = 0ull;

        float4 wv = *reinterpret_cast<const float4*>(g_w2 + base);
        NW[0] = pk(-wv.x, -wv.y);
        NW[1] = pk(-wv.z, -wv.w);
        float4 cv = *reinterpret_cast<const float4*>(g_c + base);
        Cc[0] = pk(cv.x, cv.y);
        Cc[1] = pk(cv.z, cv.w);
        float crl = g_c[(base - 1) & NMASK];   // flat roll crosses rows
        CR[0] = pk(crl,  cv.x);
        CR[1] = pk(cv.y, cv.z);
        NS[0] = pk(-(cv.x + crl),  -(cv.y + cv.x));
        NS[1] = pk(-(cv.z + cv.y), -(cv.w + cv.z));
    }

    const float TEND = 59.0f / 30.0f;
    const float H    = TEND / (float)NSTEPS;
    const u64 PH2  = pk(0.5f * H,              0.5f * H);
    const u64 PHH8 = pk(H * H * 0.125f,        H * H * 0.125f);
    const u64 PH   = pk(H,                     H);
    const u64 PHH2 = pk(H * H * 0.5f,          H * H * 0.5f);
    const u64 PHH6 = pk(H * H * (1.0f/6.0f),   H * H * (1.0f/6.0f));
    const u64 PH6  = pk(H * (1.0f/6.0f),       H * (1.0f/6.0f));
    const u64 P2   = pk(2.0f, 2.0f);
    const u64 P4   = pk(4.0f, 4.0f);

    #pragma unroll 1
    for (int stp = 0; stp < NSTEPS; ++stp) {
        u64 K1[2], K2[2], K3[2], Y2[2], Y3[2], T[2];
        accel2(Y, NW, Cc, CR, NS, lane, K1);
        #pragma unroll
        for (int i = 0; i < 2; i++)
            Y2[i] = fma2(PHH8, K1[i], fma2(PH2, V[i], Y[i]));
        accel2(Y2, NW, Cc, CR, NS, lane, K2);
        #pragma unroll
        for (int i = 0; i < 2; i++) {
            T[i]  = fma2(PH, V[i], Y[i]);
            Y3[i] = fma2(PHH2, K2[i], T[i]);
        }
        accel2(Y3, NW, Cc, CR, NS, lane, K3);
        #pragma unroll
        for (int i = 0; i < 2; i++) {
            Y[i] = fma2(PHH6, fma2(P2, K2[i], K1[i]), T[i]);
            V[i] = fma2(PH6, add2(fma2(P4, K2[i], K1[i]), K3[i]), V[i]);
        }
    }

    float o0, o1, o2, o3;
    upk(o0, o1, Y[0]); upk(o2, o3, Y[1]);
    float4 o;
    o.x = o0 * 0.4f;   // /A_NORM (=2.5), B_NORM=0
    o.y = o1 * 0.4f;
    o.z = o2 * 0.4f;
    o.w = o3 * 0.4f;
    *reinterpret_cast<float4*>(out + base) = o;
}

// ============================================================================
extern "C" void kernel_launch(void* const* d_in, const int* in_sizes, int n_in,
                              void* d_out, int out_size)
{
    const float* x     = (const float*)d_in[0];
    const float* w_in  = (const float*)d_in[1];
    const float* b_in  = (const float*)d_in[2];
    const float* w0    = (const float*)d_in[3];
    const float* b0    = (const float*)d_in[4];
    const float* w1    = (const float*)d_in[5];
    const float* b1    = (const float*)d_in[6];
    const float* w_out = (const float*)d_in[7];
    const float* b_out = (const float*)d_in[8];

    cudaFuncSetAttribute(gemm_kernel,
                         cudaFuncAttributeMaxDynamicSharedMemorySize, GEMM_SMEM);

    prep_kernel<<<192, 256>>>(x, w_in, b_in, w0, w1, w_out);
    gemm_kernel<<<128, 256, GEMM_SMEM>>>(0, 0, 1, b0);     // A0 -> A1
    gemm_kernel<<<128, 256, GEMM_SMEM>>>(1, 1, 0, b1);     // A1 -> A0
    gemm_kernel<<<128, 256, GEMM_SMEM>>>(2, 0, 0, b_out);  // A0 -> g_w2/g_c
    ode_kernel<<<(BATCH * 32) / 128, 128>>>(x, (float*)d_out);
}